// round 1
// baseline (speedup 1.0000x reference)
#include <cuda_runtime.h>
#include <math.h>

#define BS   64
#define CIN  256
#define II   1024
#define J    10
#define D    32
#define OD   320      // J*D
#define NTILE 2
#define TILE_I 512    // II / NTILE

// ---------------- scratch (static device globals; no allocation) ----------------
__device__ float g_xsum [BS*CIN];            // sum_i x[b,c,i]
__device__ float g_u    [BS*J*CIN];          // accumulated u_j = W_j^T v_j
__device__ float g_vb   [BS*J];              // accumulated v_j . bias_j
__device__ float g_ypart[BS*NTILE*J*CIN];    // per-tile partial y
__device__ float g_cpart[BS*NTILE*J];        // per-tile partial sum_i c_ji

// ---------------- f32x2 helpers ----------------
static __device__ __forceinline__ void ffma2(unsigned long long &d,
                                             unsigned long long a,
                                             unsigned long long b) {
    asm("fma.rn.f32x2 %0, %1, %2, %0;" : "+l"(d) : "l"(a), "l"(b));
}
static __device__ __forceinline__ unsigned long long dup2(float x) {
    unsigned int u = __float_as_uint(x);
    return ((unsigned long long)u << 32) | (unsigned long long)u;
}
static __device__ __forceinline__ float lo2(unsigned long long v) {
    return __uint_as_float((unsigned int)(v & 0xffffffffu));
}
static __device__ __forceinline__ float hi2(unsigned long long v) {
    return __uint_as_float((unsigned int)(v >> 32));
}

// ---------------- K1: xsum[b,c] = sum_i x[b,c,i] ----------------
__global__ void k_xsum(const float* __restrict__ x) {
    int warp = (blockIdx.x * blockDim.x + threadIdx.x) >> 5;   // row id = b*CIN + c
    int lane = threadIdx.x & 31;
    if (warp >= BS * CIN) return;
    const float4* row = (const float4*)(x + (size_t)warp * II);
    float s = 0.0f;
    #pragma unroll
    for (int k = 0; k < II / 128; k++) {
        float4 v = row[k * 32 + lane];
        s += v.x + v.y + v.z + v.w;
    }
    #pragma unroll
    for (int off = 16; off; off >>= 1) s += __shfl_xor_sync(0xffffffffu, s, off);
    if (lane == 0) g_xsum[warp] = s;
}

// ---------------- K_sv: y-reduce -> s -> squash(v) -> (u,vb update | output) ----
// one block per batch, 256 threads. mode: 0 = iter1 (y from xsum/J),
// 1 = middle iter (y from parts, accumulate u/vb), 2 = final (write v to out)
__global__ void k_sv(const float* __restrict__ W, const float* __restrict__ Wb,
                     float* __restrict__ out, int mode) {
    __shared__ __align__(16) float ysm[J * CIN];
    __shared__ float ssm[OD];
    __shared__ float vsm[OD];
    __shared__ float csum[J];
    __shared__ float coef[J];
    int b = blockIdx.x, t = threadIdx.x;

    // ---- stage 1: y[j][c] ----
    if (mode == 0) {
        float xs = g_xsum[b * CIN + t] * (1.0f / (float)J);
        #pragma unroll
        for (int j = 0; j < J; j++) ysm[j * CIN + t] = xs;
        if (t < J) csum[t] = (float)II / (float)J;
    } else {
        #pragma unroll
        for (int j = 0; j < J; j++) {
            float a = 0.0f;
            #pragma unroll
            for (int p = 0; p < NTILE; p++)
                a += g_ypart[((b * NTILE + p) * J + j) * CIN + t];
            ysm[j * CIN + t] = a;
        }
        if (t < J) {
            float a = 0.0f;
            #pragma unroll
            for (int p = 0; p < NTILE; p++) a += g_cpart[(b * NTILE + p) * J + t];
            csum[t] = a;
        }
    }
    __syncthreads();

    // ---- stage 2: s[o] = W[o,:].y[j(o),:] + csum[j]*Wb[o] ----
    for (int o = t; o < OD; o += 256) {
        int j = o >> 5;
        const float4* wr = (const float4*)(W + o * CIN);
        const float4* yr = (const float4*)(ysm + j * CIN);
        float a = 0.0f;
        #pragma unroll
        for (int c = 0; c < CIN / 4; c++) {
            float4 w4 = wr[c];
            float4 y4 = yr[c];
            a += w4.x * y4.x + w4.y * y4.y + w4.z * y4.z + w4.w * y4.w;
        }
        ssm[o] = a + csum[j] * Wb[o];
    }
    __syncthreads();

    // ---- stage 3: squash coefficient per j ----
    if (t < J) {
        float ns = 0.0f;
        #pragma unroll
        for (int d = 0; d < D; d++) { float s = ssm[t * D + d]; ns += s * s; }
        coef[t] = ns / ((1.0f + ns) * sqrtf(ns));
    }
    __syncthreads();

    for (int o = t; o < OD; o += 256) {
        float v = ssm[o] * coef[o >> 5];
        vsm[o] = v;
        if (mode == 2) out[b * OD + o] = v;   // output layout [bs, J, D]
    }
    __syncthreads();

    // ---- stage 4: accumulate u[j,c] = sum_d v[j,d]*W[jD+d, c], vb[j] ----
    if (mode != 2) {
        #pragma unroll
        for (int j = 0; j < J; j++) {
            float a = 0.0f;
            #pragma unroll
            for (int d = 0; d < D; d++)
                a += vsm[j * D + d] * W[(j * D + d) * CIN + t];
            int idx = (b * J + j) * CIN + t;
            g_u[idx] = (mode == 0) ? a : (g_u[idx] + a);
        }
        if (t < J) {
            float a = 0.0f;
            #pragma unroll
            for (int d = 0; d < D; d++) a += vsm[t * D + d] * Wb[t * D + d];
            g_vb[b * J + t] = (mode == 0) ? a : (g_vb[b * J + t] + a);
        }
    }
}

// ---------------- K_pass: logits -> softmax -> partial y, csum ----------------
// block = (tile, batch), 256 threads, each thread owns 2 spatial positions (f32x2)
__global__ void __launch_bounds__(256) k_pass(const float* __restrict__ x) {
    __shared__ __align__(16) unsigned long long us2[J * CIN];  // u duplicated-packed, 20KB
    __shared__ __align__(16) float cssm[J * TILE_I];           // softmax coeffs, 20KB
    __shared__ float vbs[J];
    int b = blockIdx.y, tile = blockIdx.x, t = threadIdx.x;

    for (int idx = t; idx < J * CIN; idx += 256)
        us2[idx] = dup2(g_u[b * J * CIN + idx]);
    if (t < J) vbs[t] = g_vb[b * J + t];
    __syncthreads();

    const float* xb = x + (size_t)b * CIN * II;
    int i0 = tile * TILE_I + t * 2;

    // ---- phase A: logits b[j, i0..i0+1] = u_j . x_i + vb_j ----
    unsigned long long acc[J];
    #pragma unroll
    for (int j = 0; j < J; j++) acc[j] = 0ull;
    #pragma unroll 4
    for (int c = 0; c < CIN; c++) {
        unsigned long long xv = *(const unsigned long long*)(xb + c * II + i0);
        #pragma unroll
        for (int j = 0; j < J; j++) ffma2(acc[j], us2[j * CIN + c], xv);
    }

    // softmax over j for the two positions
    float b0[J], b1[J];
    #pragma unroll
    for (int j = 0; j < J; j++) { b0[j] = lo2(acc[j]) + vbs[j]; b1[j] = hi2(acc[j]) + vbs[j]; }
    float m0 = b0[0], m1 = b1[0];
    #pragma unroll
    for (int j = 1; j < J; j++) { m0 = fmaxf(m0, b0[j]); m1 = fmaxf(m1, b1[j]); }
    float s0 = 0.0f, s1 = 0.0f;
    #pragma unroll
    for (int j = 0; j < J; j++) {
        b0[j] = expf(b0[j] - m0); s0 += b0[j];
        b1[j] = expf(b1[j] - m1); s1 += b1[j];
    }
    float r0 = 1.0f / s0, r1 = 1.0f / s1;
    #pragma unroll
    for (int j = 0; j < J; j++) {
        cssm[j * TILE_I + t * 2]     = b0[j] * r0;
        cssm[j * TILE_I + t * 2 + 1] = b1[j] * r1;
    }
    __syncthreads();

    // csum partial (deterministic sequential sum)
    if (t < J) {
        float a = 0.0f;
        for (int i = 0; i < TILE_I; i++) a += cssm[t * TILE_I + i];
        g_cpart[(b * NTILE + tile) * J + t] = a;
    }

    // ---- phase B: y_part[j][c=t] = sum_{i in tile} c[j,i] * x[c,i] ----
    unsigned long long acc2[J];
    #pragma unroll
    for (int j = 0; j < J; j++) acc2[j] = 0ull;
    const float* xr = xb + (size_t)t * II + tile * TILE_I;
    #pragma unroll 4
    for (int ii = 0; ii < TILE_I; ii += 2) {
        unsigned long long xv = *(const unsigned long long*)(xr + ii);
        #pragma unroll
        for (int j = 0; j < J; j++) {
            unsigned long long cv = *(const unsigned long long*)(cssm + j * TILE_I + ii);
            ffma2(acc2[j], cv, xv);
        }
    }
    #pragma unroll
    for (int j = 0; j < J; j++)
        g_ypart[((b * NTILE + tile) * J + j) * CIN + t] = lo2(acc2[j]) + hi2(acc2[j]);
}

// ---------------- launch ----------------
extern "C" void kernel_launch(void* const* d_in, const int* in_sizes, int n_in,
                              void* d_out, int out_size) {
    const float* x  = (const float*)d_in[0];   // [64,256,32,32]
    const float* W  = (const float*)d_in[1];   // [320,256]
    const float* Wb = (const float*)d_in[2];   // [320]
    float* out = (float*)d_out;                // [64,10,32]

    k_xsum<<<BS * CIN / 8, 256>>>(x);
    k_sv  <<<BS, 256>>>(W, Wb, out, 0);        // iter1: v1, u1, vb1
    k_pass<<<dim3(NTILE, BS), 256>>>(x);       // iter2 logits+softmax+y
    k_sv  <<<BS, 256>>>(W, Wb, out, 1);        // iter2: v2, u+=u2, vb+=vb2
    k_pass<<<dim3(NTILE, BS), 256>>>(x);       // iter3 logits+softmax+y
    k_sv  <<<BS, 256>>>(W, Wb, out, 2);        // iter3: v3 -> out
}

// round 2
// speedup vs baseline: 2.5678x; 2.5678x over previous
#include <cuda_runtime.h>
#include <math.h>

#define BS   64
#define CIN  256
#define II   1024
#define J    10
#define D    32
#define OD   320      // J*D
#define NTILE 4
#define TILE_I 256    // II / NTILE

typedef unsigned long long ull;

// ---------------- scratch (static device globals; no allocation) ----------------
__device__ float g_xsum [BS*CIN];            // sum_i x[b,c,i]
__device__ float g_u    [BS*J*CIN];          // accumulated u_j = W_j^T v_j (running sum over iters)
__device__ float g_vb   [BS*J];              // accumulated v_j . bias_j
__device__ float g_ypart[BS*NTILE*J*CIN];    // per-tile partial y
__device__ float g_cpart[BS*NTILE*J];        // per-tile partial sum_i c_ji

// ---------------- f32x2 helpers ----------------
static __device__ __forceinline__ void ffma2(ull &d, ull a, ull b) {
    asm("fma.rn.f32x2 %0, %1, %2, %0;" : "+l"(d) : "l"(a), "l"(b));
}
static __device__ __forceinline__ ull pack2(float lo, float hi) {
    ull r;
    asm("mov.b64 %0, {%1, %2};" : "=l"(r) : "f"(lo), "f"(hi));
    return r;
}
static __device__ __forceinline__ float lo2(ull v) {
    return __uint_as_float((unsigned int)(v & 0xffffffffu));
}
static __device__ __forceinline__ float hi2(ull v) {
    return __uint_as_float((unsigned int)(v >> 32));
}

// ---------------- K1: xsum[b,c] = sum_i x[b,c,i] ----------------
__global__ void k_xsum(const float* __restrict__ x) {
    int warp = (blockIdx.x * blockDim.x + threadIdx.x) >> 5;   // row id = b*CIN + c
    int lane = threadIdx.x & 31;
    if (warp >= BS * CIN) return;
    const float4* row = (const float4*)(x + (size_t)warp * II);
    float s = 0.0f;
    #pragma unroll
    for (int k = 0; k < II / 128; k++) {
        float4 v = row[k * 32 + lane];
        s += v.x + v.y + v.z + v.w;
    }
    #pragma unroll
    for (int off = 16; off; off >>= 1) s += __shfl_xor_sync(0xffffffffu, s, off);
    if (lane == 0) g_xsum[warp] = s;
}

// ---------------- K_sv: per (b,j): y-reduce -> s -> squash(v) -> u,vb | out ----
// grid (J, BS), 256 threads. mode: 0 iter1 (y=xsum/J, init u/vb),
// 1 middle (y from parts, accumulate u/vb), 2 final (write v to out)
__global__ void __launch_bounds__(256) k_sv(const float* __restrict__ W,
                                            const float* __restrict__ Wb,
                                            float* __restrict__ out, int mode) {
    int j = blockIdx.x, b = blockIdx.y, t = threadIdx.x;
    int wid = t >> 5, lane = t & 31;
    __shared__ __align__(16) float ysm[CIN];
    __shared__ float ssm[D];
    __shared__ float vsm[D];
    __shared__ float csum_s;

    // ---- y[c] for this (b,j) ----
    float yv;
    if (mode == 0) {
        yv = g_xsum[b * CIN + t] * (1.0f / (float)J);
        if (t == 0) csum_s = (float)II / (float)J;
    } else {
        yv = 0.0f;
        #pragma unroll
        for (int p = 0; p < NTILE; p++)
            yv += g_ypart[((b * NTILE + p) * J + j) * CIN + t];
        if (t == 0) {
            float a = 0.0f;
            #pragma unroll
            for (int p = 0; p < NTILE; p++) a += g_cpart[(b * NTILE + p) * J + j];
            csum_s = a;
        }
    }
    ysm[t] = yv;
    __syncthreads();
    float csum = csum_s;

    // ---- s[d] = W[jD+d,:] . y + csum*Wb[jD+d]; warp w handles d = w, w+8, ... ----
    for (int d = wid; d < D; d += 8) {
        const float4* wr = (const float4*)(W + (size_t)(j * D + d) * CIN);
        const float4* yr = (const float4*)ysm;
        float4 w0 = wr[lane * 2], w1 = wr[lane * 2 + 1];
        float4 y0 = yr[lane * 2], y1 = yr[lane * 2 + 1];
        float a = w0.x * y0.x + w0.y * y0.y + w0.z * y0.z + w0.w * y0.w
                + w1.x * y1.x + w1.y * y1.y + w1.z * y1.z + w1.w * y1.w;
        #pragma unroll
        for (int off = 16; off; off >>= 1) a += __shfl_xor_sync(0xffffffffu, a, off);
        if (lane == 0) ssm[d] = a + csum * Wb[j * D + d];
    }
    __syncthreads();

    // ---- squash + v (warp 0) ----
    if (wid == 0) {
        float s = ssm[lane];
        float ns = s * s;
        #pragma unroll
        for (int off = 16; off; off >>= 1) ns += __shfl_xor_sync(0xffffffffu, ns, off);
        float coef = ns / ((1.0f + ns) * sqrtf(ns));
        float v = s * coef;
        vsm[lane] = v;
        if (mode == 2) {
            out[(b * J + j) * D + lane] = v;
        } else {
            float pv = v * Wb[j * D + lane];
            #pragma unroll
            for (int off = 16; off; off >>= 1) pv += __shfl_xor_sync(0xffffffffu, pv, off);
            if (lane == 0) g_vb[b * J + j] = (mode == 0) ? pv : g_vb[b * J + j] + pv;
        }
    }
    __syncthreads();

    // ---- u[c] = sum_d v[d] * W[jD+d, c] ----
    if (mode != 2) {
        float a = 0.0f;
        #pragma unroll
        for (int d = 0; d < D; d++)
            a = fmaf(vsm[d], W[(size_t)(j * D + d) * CIN + t], a);
        int idx = (b * J + j) * CIN + t;
        g_u[idx] = (mode == 0) ? a : g_u[idx] + a;
    }
}

// ---------------- K_pass: logits -> softmax -> partial y, csum ----------------
// grid (NTILE, BS), 256 threads. phase A: thread owns one i. phase B: thread owns
// one c, consuming x chunks staged in swizzled smem (coalesced global loads).
__global__ void __launch_bounds__(256) k_pass(const float* __restrict__ x) {
    __shared__ __align__(16) ull   usm[J * (CIN / 2)];     // u packed in c-pairs, 10KB
    __shared__ float vbs[J];
    __shared__ __align__(16) float cssm[J * TILE_I];       // softmax coeffs [j][i], 10KB
    __shared__ __align__(16) float xsm[CIN * 32];          // 32-i chunk, swizzled, 32KB

    int b = blockIdx.y, tile = blockIdx.x, t = threadIdx.x;
    int wid = t >> 5, lane = t & 31;

    const ull* up = (const ull*)(g_u + (size_t)b * J * CIN);
    for (int idx = t; idx < J * CIN / 2; idx += 256) usm[idx] = up[idx];
    if (t < J) vbs[t] = g_vb[b * J + t];
    __syncthreads();

    const float* xb = x + (size_t)b * CIN * II;
    int i0 = tile * TILE_I;

    // ---- phase A: logit[j] = u_j . x[:, i] + vb_j ; i = i0 + t ----
    {
        const float* xi = xb + i0 + t;
        ull acc[J];
        #pragma unroll
        for (int j = 0; j < J; j++) acc[j] = 0ull;
        #pragma unroll 2
        for (int cq = 0; cq < CIN / 4; cq++) {
            float x0 = __ldg(xi + (size_t)(4 * cq + 0) * II);
            float x1 = __ldg(xi + (size_t)(4 * cq + 1) * II);
            float x2 = __ldg(xi + (size_t)(4 * cq + 2) * II);
            float x3 = __ldg(xi + (size_t)(4 * cq + 3) * II);
            ull x01 = pack2(x0, x1), x23 = pack2(x2, x3);
            #pragma unroll
            for (int j = 0; j < J; j++) {
                ulonglong2 u4 = *(const ulonglong2*)(usm + j * (CIN / 2) + cq * 2);
                ffma2(acc[j], u4.x, x01);
                ffma2(acc[j], u4.y, x23);
            }
        }
        float lg[J];
        #pragma unroll
        for (int j = 0; j < J; j++) lg[j] = lo2(acc[j]) + hi2(acc[j]) + vbs[j];
        float m = lg[0];
        #pragma unroll
        for (int j = 1; j < J; j++) m = fmaxf(m, lg[j]);
        float s = 0.0f;
        #pragma unroll
        for (int j = 0; j < J; j++) { lg[j] = __expf(lg[j] - m); s += lg[j]; }
        float r = 1.0f / s;
        #pragma unroll
        for (int j = 0; j < J; j++) cssm[j * TILE_I + t] = lg[j] * r;
    }
    __syncthreads();

    // ---- csum partials (warp-strided over j, lanes over i) ----
    for (int j = wid; j < J; j += 8) {
        const float4* p = (const float4*)(cssm + j * TILE_I);
        float4 a = p[lane * 2], b4 = p[lane * 2 + 1];
        float sc = a.x + a.y + a.z + a.w + b4.x + b4.y + b4.z + b4.w;
        #pragma unroll
        for (int off = 16; off; off >>= 1) sc += __shfl_xor_sync(0xffffffffu, sc, off);
        if (lane == 0) g_cpart[(b * NTILE + tile) * J + j] = sc;
    }

    // ---- phase B: y[j][c=t] = sum_i c[j,i] * x[c,i], chunked over i ----
    ull yacc[J][2];
    #pragma unroll
    for (int j = 0; j < J; j++) { yacc[j][0] = 0ull; yacc[j][1] = 0ull; }

    #pragma unroll 1
    for (int ch = 0; ch < TILE_I / 32; ch++) {
        __syncthreads();  // previous chunk fully consumed
        // cooperative coalesced load of x[all c][32 i] into swizzled smem
        #pragma unroll
        for (int sw = 0; sw < 8; sw++) {
            int row = sw * 32 + (t >> 3);
            int q   = t & 7;                      // 16B quad within the 128B row
            float4 v = *(const float4*)(xb + (size_t)row * II + i0 + ch * 32 + q * 4);
            int sidx = row * 32 + ((q ^ (row & 7)) << 2);
            *(float4*)(xsm + sidx) = v;
        }
        __syncthreads();
        // accumulate: thread t = channel t reads its swizzled row
        #pragma unroll
        for (int g = 0; g < 8; g++) {             // 4 i per group
            int sidx = t * 32 + ((g ^ (t & 7)) << 2);
            float4 xv = *(const float4*)(xsm + sidx);
            ull x01 = pack2(xv.x, xv.y), x23 = pack2(xv.z, xv.w);
            int ii = ch * 32 + g * 4;
            #pragma unroll
            for (int j = 0; j < J; j++) {
                float4 cv = *(const float4*)(cssm + j * TILE_I + ii);  // warp-uniform
                ffma2(yacc[j][0], pack2(cv.x, cv.y), x01);
                ffma2(yacc[j][1], pack2(cv.z, cv.w), x23);
            }
        }
    }
    #pragma unroll
    for (int j = 0; j < J; j++)
        g_ypart[((b * NTILE + tile) * J + j) * CIN + t] =
            (lo2(yacc[j][0]) + hi2(yacc[j][0])) + (lo2(yacc[j][1]) + hi2(yacc[j][1]));
}

// ---------------- launch ----------------
extern "C" void kernel_launch(void* const* d_in, const int* in_sizes, int n_in,
                              void* d_out, int out_size) {
    const float* x  = (const float*)d_in[0];   // [64,256,32,32]
    const float* W  = (const float*)d_in[1];   // [320,256]
    const float* Wb = (const float*)d_in[2];   // [320]
    float* out = (float*)d_out;                // [64,10,32]

    k_xsum<<<BS * CIN / 8, 256>>>(x);
    k_sv  <<<dim3(J, BS), 256>>>(W, Wb, out, 0);   // iter1: v1, u1, vb1
    k_pass<<<dim3(NTILE, BS), 256>>>(x);           // iter2 logits+softmax+y
    k_sv  <<<dim3(J, BS), 256>>>(W, Wb, out, 1);   // iter2: v2, u+=, vb+=
    k_pass<<<dim3(NTILE, BS), 256>>>(x);           // iter3 logits+softmax+y
    k_sv  <<<dim3(J, BS), 256>>>(W, Wb, out, 2);   // iter3: v3 -> out
}